// round 14
// baseline (speedup 1.0000x reference)
#include <cuda_runtime.h>
#include <cuda_bf16.h>
#include <cstdint>

#define O_NUM 50000
#define T_NUM 200000
#define N_NUM (O_NUM + T_NUM)
#define D_DIM 128
#define NPART 196
#define WBLK  64
#define RSQRT2F 0.7071067811865476f

// ---------------- scratch ----------------
__device__ __nv_bfloat16 g_yh[(size_t)T_NUM * D_DIM];
__device__ __nv_bfloat16 g_yl[(size_t)T_NUM * D_DIM];
__device__ __nv_bfloat16 g_wh[D_DIM * D_DIM];
__device__ __nv_bfloat16 g_wl[D_DIM * D_DIM];
__device__ float     g_dinv[O_NUM];
__device__ int       g_counts[O_NUM];
__device__ int       g_offs[O_NUM + 1];
__device__ int       g_cursor[O_NUM];
__device__ int       g_sorted[T_NUM];
__device__ int       g_part[NPART];
__device__ int       g_stride;
__device__ int       g_doff;

__device__ __forceinline__ int edge_src(const int* e32, int t, int stride) {
    return __ldg(e32 + (size_t)stride * t);
}
__device__ __forceinline__ int edge_dst(const int* e32, int t, int stride, int doff) {
    return __ldg(e32 + (size_t)stride * t + doff);
}
__device__ __forceinline__ const float* row_ptr(int k, const float* obj, const float* pred) {
    return (k < O_NUM) ? (obj + (size_t)k * D_DIM) : (pred + (size_t)(k - O_NUM) * D_DIM);
}

// ---------------- K1: prep ----------------
__global__ void prep_kernel(const float* __restrict__ W, const int* __restrict__ e32) {
    int b = blockIdx.x;
    if (b < NPART) {
        int i = b * 256 + threadIdx.x;
        if (i < O_NUM) { g_counts[i] = 0; g_cursor[i] = 0; }
    } else if (b < NPART + WBLK) {
        int i = (b - NPART) * 256 + threadIdx.x;
        float w = W[i];
        __nv_bfloat16 h = __float2bfloat16(w);
        g_wh[i] = h;
        g_wl[i] = __float2bfloat16(w - __bfloat162float(h));
    } else {
        if (threadIdx.x < 32) {
            int acc = 0;
            for (int i = threadIdx.x; i < 4096; i += 32) acc |= e32[2 * i + 1];
            #pragma unroll
            for (int off = 16; off; off >>= 1) acc |= __shfl_xor_sync(0xFFFFFFFFu, acc, off);
            if (threadIdx.x == 0) {
                g_stride = acc ? 2 : 4;
                g_doff   = acc ? 1 : 2;
            }
        }
    }
}

// ---------------- K2: histogram ----------------
__global__ void hist_kernel(const int* __restrict__ e32) {
    int t = blockIdx.x * blockDim.x + threadIdx.x;
    if (t < T_NUM) {
        int d = edge_dst(e32, t, g_stride, g_doff);
        atomicAdd(&g_counts[d], 1);
    }
}

// ---------------- K3: per-block exclusive scan ----------------
__global__ __launch_bounds__(256) void scan_block_kernel() {
    int t = threadIdx.x;
    int i = blockIdx.x * 256 + t;
    int lane = t & 31, w = t >> 5;
    int v = (i < O_NUM) ? g_counts[i] : 0;

    int iv = v;
    #pragma unroll
    for (int off = 1; off < 32; off <<= 1) {
        int n = __shfl_up_sync(0xFFFFFFFFu, iv, off);
        if (lane >= off) iv += n;
    }
    __shared__ int ws[8];
    if (lane == 31) ws[w] = iv;
    __syncthreads();
    if (w == 0 && lane < 8) {
        int x = ws[lane];
        #pragma unroll
        for (int off = 1; off < 8; off <<= 1) {
            int n = __shfl_up_sync(0x000000FFu, x, off);
            if (lane >= off) x += n;
        }
        ws[lane] = x;
    }
    __syncthreads();
    int excl = iv - v + (w ? ws[w - 1] : 0);
    if (i < O_NUM) g_offs[i] = excl;
    if (t == 255) g_part[blockIdx.x] = excl + v;
}

// ---------------- K4: fixup + dinv ----------------
__global__ __launch_bounds__(256) void scan_fix_kernel() {
    int b = blockIdx.x;
    int t = threadIdx.x;
    int lane = t & 31, w = t >> 5;

    int v = (t < b) ? g_part[t] : 0;
    #pragma unroll
    for (int off = 16; off; off >>= 1) v += __shfl_xor_sync(0xFFFFFFFFu, v, off);
    __shared__ int ws[8];
    if (lane == 0) ws[w] = v;
    __syncthreads();
    __shared__ int base_s;
    if (t == 0) {
        int s = 0;
        #pragma unroll
        for (int q = 0; q < 8; q++) s += ws[q];
        base_s = s;
    }
    __syncthreads();
    int base = base_s;

    int i = b * 256 + t;
    if (i < O_NUM) {
        g_offs[i] += base;
        g_dinv[i] = rsqrtf(2.0f + (float)g_counts[i]);
    }
    if (b == NPART - 1 && t == 0) g_offs[O_NUM] = base + g_part[NPART - 1];
}

// ---------------- K5: easy rows ----------------
__global__ __launch_bounds__(256) void agg_easy_kernel(const float* __restrict__ obj,
                                                       const float* __restrict__ pred,
                                                       const int* __restrict__ e32) {
    int gwarp = (blockIdx.x * blockDim.x + threadIdx.x) >> 5;
    int lane  = threadIdx.x & 31;
    if (gwarp >= T_NUM - O_NUM) return;
    int n = O_NUM + gwarp;

    const float4* xn = reinterpret_cast<const float4*>(pred + (size_t)gwarp * D_DIM);
    float4 a = __ldg(xn + lane);
    int s = edge_src(e32, n, g_stride);
    float ds = g_dinv[s];
    const float4* xs = reinterpret_cast<const float4*>(obj + (size_t)s * D_DIM);
    float4 v = __ldg(xs + lane);

    const float dn = RSQRT2F;
    float4 acc;
    acc.x = (fmaf(v.x, ds, a.x * dn)) * dn;
    acc.y = (fmaf(v.y, ds, a.y * dn)) * dn;
    acc.z = (fmaf(v.z, ds, a.z * dn)) * dn;
    acc.w = (fmaf(v.w, ds, a.w * dn)) * dn;

    float v4[4] = {acc.x, acc.y, acc.z, acc.w};
    alignas(8) __nv_bfloat16 h[4];
    alignas(8) __nv_bfloat16 l[4];
    #pragma unroll
    for (int q = 0; q < 4; q++) {
        h[q] = __float2bfloat16(v4[q]);
        l[q] = __float2bfloat16(v4[q] - __bfloat162float(h[q]));
    }
    size_t base = (size_t)n * D_DIM + lane * 4;
    *reinterpret_cast<uint2*>(g_yh + base) = *reinterpret_cast<const uint2*>(h);
    *reinterpret_cast<uint2*>(g_yl + base) = *reinterpret_cast<const uint2*>(l);
}

// ---------------- K6: counting-sort scatter ----------------
__global__ void csr_scatter_kernel(const int* __restrict__ e32) {
    int t = blockIdx.x * blockDim.x + threadIdx.x;
    if (t < T_NUM) {
        int d = edge_dst(e32, t, g_stride, g_doff);
        int pos = g_offs[d] + atomicAdd(&g_cursor[d], 1);
        g_sorted[pos] = t;
    }
}

// ---------------- K7: hard rows (bucket chain hoisted first) ----------------
__global__ __launch_bounds__(256) void agg_hard_kernel(const float* __restrict__ obj,
                                                       const float* __restrict__ pred,
                                                       const int* __restrict__ e32) {
    int n = (blockIdx.x * blockDim.x + threadIdx.x) >> 5;
    int lane  = threadIdx.x & 31;
    if (n >= O_NUM) return;

    // start the dependent bucket chain FIRST
    int beg = g_offs[n];
    int cnt = g_offs[n + 1] - beg;
    int m0 = cnt > 8 ? 8 : cnt;
    int   kid0 = 0;
    float dkl0 = 0.0f;
    if (lane < m0) {
        kid0 = g_sorted[beg + lane];
        dkl0 = (kid0 < O_NUM) ? g_dinv[kid0] : RSQRT2F;
    }

    // independent loads issue while the chain resolves
    float dn = g_dinv[n];
    const float4* xn = reinterpret_cast<const float4*>(obj + (size_t)n * D_DIM);
    float4 a = __ldg(xn + lane);
    int s = edge_src(e32, n, g_stride);
    float ds = g_dinv[s];
    const float4* xs = reinterpret_cast<const float4*>(obj + (size_t)s * D_DIM);
    float4 v1 = __ldg(xs + lane);

    float4 acc;
    acc.x = fmaf(v1.x, ds, a.x * dn);
    acc.y = fmaf(v1.y, ds, a.y * dn);
    acc.z = fmaf(v1.z, ds, a.z * dn);
    acc.w = fmaf(v1.w, ds, a.w * dn);

    for (int bb = 0; bb < cnt; bb += 8) {
        int m = cnt - bb; if (m > 8) m = 8;
        int kid; float dkl;
        if (bb == 0) { kid = kid0; dkl = dkl0; }
        else {
            kid = 0; dkl = 0.0f;
            if (lane < m) {
                kid = g_sorted[beg + bb + lane];
                dkl = (kid < O_NUM) ? g_dinv[kid] : RSQRT2F;
            }
        }
        #pragma unroll
        for (int i = 0; i < 8; i++) {
            if (i >= m) break;
            int   k  = __shfl_sync(0xFFFFFFFFu, kid, i);
            float dk = __shfl_sync(0xFFFFFFFFu, dkl, i);
            const float4* xk = reinterpret_cast<const float4*>(row_ptr(k, obj, pred));
            float4 v = __ldg(xk + lane);
            acc.x = fmaf(v.x, dk, acc.x);
            acc.y = fmaf(v.y, dk, acc.y);
            acc.z = fmaf(v.z, dk, acc.z);
            acc.w = fmaf(v.w, dk, acc.w);
        }
    }

    acc.x *= dn; acc.y *= dn; acc.z *= dn; acc.w *= dn;

    float v4[4] = {acc.x, acc.y, acc.z, acc.w};
    alignas(8) __nv_bfloat16 h[4];
    alignas(8) __nv_bfloat16 l[4];
    #pragma unroll
    for (int i = 0; i < 4; i++) {
        h[i] = __float2bfloat16(v4[i]);
        l[i] = __float2bfloat16(v4[i] - __bfloat162float(h[i]));
    }
    size_t base = (size_t)n * D_DIM + lane * 4;
    *reinterpret_cast<uint2*>(g_yh + base) = *reinterpret_cast<const uint2*>(h);
    *reinterpret_cast<uint2*>(g_yl + base) = *reinterpret_cast<const uint2*>(l);
}

// ============ K8: persistent GEMM (tile range), W in registers ============
__device__ __forceinline__ void mma16816(float c[4], const uint32_t a[4], const uint32_t b[2]) {
    asm("mma.sync.aligned.m16n8k16.row.col.f32.bf16.bf16.f32 "
        "{%0,%1,%2,%3}, {%4,%5,%6,%7}, {%8,%9}, {%0,%1,%2,%3};"
        : "+f"(c[0]), "+f"(c[1]), "+f"(c[2]), "+f"(c[3])
        : "r"(a[0]), "r"(a[1]), "r"(a[2]), "r"(a[3]), "r"(b[0]), "r"(b[1]));
}

#define LDSY 136
#define TILE_M 32
#define SMEM_W_HALF (128 * LDSY)
#define SMEM_A_HALF (TILE_M * LDSY)
#define GEMM_SMEM_BYTES ((2 * SMEM_W_HALF + 4 * SMEM_A_HALF) * 2)

#define NT_TILES ((N_NUM + TILE_M - 1) / TILE_M)    // 7813
#define TILE_LOW_END 1563                            // tiles [0,1563) cover rows 0..50015
#define GEMM_GRID 148

__device__ __forceinline__ uint32_t lds32(const __nv_bfloat16* p) {
    return *reinterpret_cast<const uint32_t*>(p);
}
__device__ __forceinline__ void cp_async16(uint32_t dst, const void* src) {
    asm volatile("cp.async.cg.shared.global [%0], [%1], 16;" :: "r"(dst), "l"(src));
}
#define CP_COMMIT() asm volatile("cp.async.commit_group;" ::: "memory")
#define CP_WAIT1()  asm volatile("cp.async.wait_group 1;" ::: "memory")

extern __shared__ char sm_raw[];

__global__ __launch_bounds__(512, 1) void gemm_wreg_kernel(const float* __restrict__ pred,
                                                           const float* __restrict__ bias,
                                                           float* __restrict__ out,
                                                           int t_begin, int t_end) {
    __nv_bfloat16* sWh = reinterpret_cast<__nv_bfloat16*>(sm_raw);
    __nv_bfloat16* sWl = sWh + SMEM_W_HALF;
    __nv_bfloat16* sA  = sWl + SMEM_W_HALF;

    int tid  = threadIdx.x;
    int warp = tid >> 5, lane = tid & 31;
    int g  = lane >> 2;
    int tg = lane & 3;
    int band = warp >> 3;
    int cg   = warp & 7;

    #pragma unroll
    for (int it = 0; it < 8; it++) {
        int idx = tid + it * 512;
        int half = idx >> 11;
        int r    = (idx >> 4) & 127;
        int seg  = idx & 15;
        const __nv_bfloat16* src = (half ? g_wl : g_wh) + r * D_DIM + seg * 8;
        __nv_bfloat16* dst = (half ? sWl : sWh) + r * LDSY + seg * 8;
        *reinterpret_cast<uint4*>(dst) = *reinterpret_cast<const uint4*>(src);
    }
    __syncthreads();

    uint32_t wfh[8][2][2], wfl[8][2][2];
    #pragma unroll
    for (int kt = 0; kt < 8; kt++) {
        #pragma unroll
        for (int n = 0; n < 2; n++) {
            int cw = cg * 16 + n * 8 + g;
            const __nv_bfloat16* pH = sWh + cw * LDSY + kt * 16 + tg * 2;
            const __nv_bfloat16* pL = sWl + cw * LDSY + kt * 16 + tg * 2;
            wfh[kt][n][0] = lds32(pH); wfh[kt][n][1] = lds32(pH + 8);
            wfl[kt][n][0] = lds32(pL); wfl[kt][n][1] = lds32(pL + 8);
        }
    }

    float2 bb[2];
    #pragma unroll
    for (int n = 0; n < 2; n++)
        bb[n] = __ldg(reinterpret_cast<const float2*>(bias + cg * 16 + n * 8 + tg * 2));

    uint32_t sA_u32 = (uint32_t)__cvta_generic_to_shared(sA);

    auto stage = [&](int tile, int buf) {
        int rowbase = tile * TILE_M;
        #pragma unroll
        for (int q = 0; q < 2; q++) {
            int idx = tid + q * 512;
            int half = idx >> 9;
            int r    = (idx >> 4) & 31;
            int seg  = idx & 15;
            int grow = rowbase + r;
            uint32_t off = ((buf * 2 + half) * SMEM_A_HALF + r * LDSY + seg * 8) * 2;
            if (grow < T_NUM) {
                const __nv_bfloat16* src = (half ? g_yl : g_yh) + (size_t)grow * D_DIM + seg * 8;
                cp_async16(sA_u32 + off, src);
            } else {
                alignas(16) __nv_bfloat16 v[8];
                if (grow < N_NUM) {
                    const float4* s = reinterpret_cast<const float4*>(
                        pred + (size_t)(grow - O_NUM) * D_DIM + seg * 8);
                    float4 f0 = __ldg(s), f1 = __ldg(s + 1);
                    float ff[8] = {f0.x, f0.y, f0.z, f0.w, f1.x, f1.y, f1.z, f1.w};
                    #pragma unroll
                    for (int p = 0; p < 8; p++) {
                        __nv_bfloat16 hh = __float2bfloat16(ff[p]);
                        v[p] = half ? __float2bfloat16(ff[p] - __bfloat162float(hh)) : hh;
                    }
                } else {
                    #pragma unroll
                    for (int p = 0; p < 8; p++) v[p] = __float2bfloat16(0.f);
                }
                *reinterpret_cast<uint4*>(reinterpret_cast<char*>(sA) + off) =
                    *reinterpret_cast<const uint4*>(v);
            }
        }
    };

    int t0 = t_begin + blockIdx.x;
    if (t0 < t_end) stage(t0, 0);
    CP_COMMIT();

    int buf = 0;
    for (int t = t0; t < t_end; t += GEMM_GRID) {
        int tn = t + GEMM_GRID;
        if (tn < t_end) stage(tn, buf ^ 1);
        CP_COMMIT();
        CP_WAIT1();
        __syncthreads();

        const __nv_bfloat16* bAh = sA + (buf * 2 + 0) * SMEM_A_HALF;
        const __nv_bfloat16* bAl = sA + (buf * 2 + 1) * SMEM_A_HALF;
        const __nv_bfloat16* aH0 = bAh + (band * 16 + g) * LDSY;
        const __nv_bfloat16* aL0 = bAl + (band * 16 + g) * LDSY;

        float c[2][4];
        #pragma unroll
        for (int n = 0; n < 2; n++)
            #pragma unroll
            for (int q = 0; q < 4; q++) c[n][q] = 0.0f;

        #pragma unroll
        for (int kt = 0; kt < 8; kt++) {
            int k = kt * 16;
            uint32_t ah[4], al[4];
            ah[0] = lds32(aH0 + k + tg * 2);
            ah[1] = lds32(aH0 + 8 * LDSY + k + tg * 2);
            ah[2] = lds32(aH0 + k + 8 + tg * 2);
            ah[3] = lds32(aH0 + 8 * LDSY + k + 8 + tg * 2);
            al[0] = lds32(aL0 + k + tg * 2);
            al[1] = lds32(aL0 + 8 * LDSY + k + tg * 2);
            al[2] = lds32(aL0 + k + 8 + tg * 2);
            al[3] = lds32(aL0 + 8 * LDSY + k + 8 + tg * 2);

            #pragma unroll
            for (int n = 0; n < 2; n++) {
                mma16816(c[n], ah, wfh[kt][n]);
                mma16816(c[n], al, wfh[kt][n]);
                mma16816(c[n], ah, wfl[kt][n]);
            }
        }

        int rowbase = t * TILE_M;
        int r0 = rowbase + band * 16 + g;
        int r1 = r0 + 8;
        #pragma unroll
        for (int n = 0; n < 2; n++) {
            int col = cg * 16 + n * 8 + tg * 2;
            if (r0 < N_NUM) {
                float2 o = make_float2(c[n][0] + bb[n].x, c[n][1] + bb[n].y);
                *reinterpret_cast<float2*>(out + (size_t)r0 * D_DIM + col) = o;
            }
            if (r1 < N_NUM) {
                float2 o = make_float2(c[n][2] + bb[n].x, c[n][3] + bb[n].y);
                *reinterpret_cast<float2*>(out + (size_t)r1 * D_DIM + col) = o;
            }
        }
        buf ^= 1;
        __syncthreads();
    }
}

// ---------------- launch: fork-join + split GEMM overlap ----------------
static cudaStream_t g_s2 = nullptr;
static cudaEvent_t  g_evFork = nullptr, g_evJoin = nullptr;

extern "C" void kernel_launch(void* const* d_in, const int* in_sizes, int n_in,
                              void* d_out, int out_size) {
    const float* obj   = (const float*)d_in[0];
    const float* pred  = (const float*)d_in[1];
    const int*   e32   = (const int*)d_in[2];
    const float* W     = (const float*)d_in[3];
    const float* bias  = (const float*)d_in[4];
    float*       out   = (float*)d_out;

    if (g_s2 == nullptr) {
        cudaStreamCreateWithFlags(&g_s2, cudaStreamNonBlocking);
        cudaEventCreateWithFlags(&g_evFork, cudaEventDisableTiming);
        cudaEventCreateWithFlags(&g_evJoin, cudaEventDisableTiming);
        cudaFuncSetAttribute(gemm_wreg_kernel,
                             cudaFuncAttributeMaxDynamicSharedMemorySize, GEMM_SMEM_BYTES);
    }

    // serial prefix (stream 0)
    prep_kernel<<<NPART + WBLK + 1, 256>>>(W, e32);
    hist_kernel<<<(T_NUM + 255) / 256, 256>>>(e32);
    scan_block_kernel<<<NPART, 256>>>();
    scan_fix_kernel<<<NPART, 256>>>();

    // fork
    cudaEventRecord(g_evFork, 0);
    cudaStreamWaitEvent(g_s2, g_evFork, 0);

    // branch B (s2): scatter -> hard rows
    csr_scatter_kernel<<<(T_NUM + 255) / 256, 256, 0, g_s2>>>(e32);
    agg_hard_kernel<<<(O_NUM + 7) / 8, 256, 0, g_s2>>>(obj, pred, e32);
    cudaEventRecord(g_evJoin, g_s2);

    // branch A (stream 0): easy rows, then GEMM over rows >= 50016 (easy+identity only)
    agg_easy_kernel<<<(T_NUM - O_NUM + 7) / 8, 256>>>(obj, pred, e32);
    gemm_wreg_kernel<<<GEMM_GRID, 512, GEMM_SMEM_BYTES>>>(pred, bias, out,
                                                          TILE_LOW_END, NT_TILES);

    // join, then GEMM over rows 0..50015 (needs hard rows)
    cudaStreamWaitEvent(0, g_evJoin, 0);
    gemm_wreg_kernel<<<GEMM_GRID, 512, GEMM_SMEM_BYTES>>>(pred, bias, out,
                                                          0, TILE_LOW_END);
}

// round 15
// speedup vs baseline: 1.0332x; 1.0332x over previous
#include <cuda_runtime.h>
#include <cuda_bf16.h>
#include <cstdint>

#define O_NUM 50000
#define T_NUM 200000
#define N_NUM (O_NUM + T_NUM)
#define D_DIM 128
#define NPART 196
#define HBLK  782            // ceil(T_NUM/256)
#define WBLK  64
#define RSQRT2F 0.7071067811865476f

// ---------------- scratch (zero-initialized at module load) ----------------
__device__ __nv_bfloat16 g_yh[(size_t)T_NUM * D_DIM];
__device__ __nv_bfloat16 g_yl[(size_t)T_NUM * D_DIM];
__device__ __nv_bfloat16 g_wh[D_DIM * D_DIM];
__device__ __nv_bfloat16 g_wl[D_DIM * D_DIM];
__device__ float     g_dinv[O_NUM];
__device__ int       g_counts[O_NUM];   // invariant: zero at call entry (self-cleaning)
__device__ int       g_offs[O_NUM + 1];
__device__ int       g_cursor[O_NUM];   // invariant: zero at call entry (self-cleaning)
__device__ int       g_sorted[T_NUM];
__device__ int       g_part[NPART];
__device__ int       g_stride;
__device__ int       g_doff;

__device__ __forceinline__ int edge_src(const int* e32, int t, int stride) {
    return __ldg(e32 + (size_t)stride * t);
}
__device__ __forceinline__ int edge_dst(const int* e32, int t, int stride, int doff) {
    return __ldg(e32 + (size_t)stride * t + doff);
}
__device__ __forceinline__ const float* row_ptr(int k, const float* obj, const float* pred) {
    return (k < O_NUM) ? (obj + (size_t)k * D_DIM) : (pred + (size_t)(k - O_NUM) * D_DIM);
}

// ---------------- K1: hist + W split + global dtype detect (one launch) ----------------
// blocks [0,HBLK): histogram with per-block inline dtype detect
// blocks [HBLK, HBLK+WBLK): W hi/lo split
// block  HBLK+WBLK: global dtype detect (for later launches)
__global__ void hist_all_kernel(const float* __restrict__ W, const int* __restrict__ e32) {
    int b = blockIdx.x;
    int tid = threadIdx.x;
    if (b < HBLK) {
        // inline detect over this block's odd words (guarded to min-valid extent)
        int idx = 512 * b + 2 * tid + 1;         // odd word within this block's window
        int v = (idx < 2 * T_NUM) ? e32[idx] : 0;
        int any = __syncthreads_or(v);
        int stride = any ? 2 : 4;
        int doff   = any ? 1 : 2;
        int t = b * 256 + tid;
        if (t < T_NUM) {
            int d = e32[(size_t)stride * t + doff];
            atomicAdd(&g_counts[d], 1);
        }
    } else if (b < HBLK + WBLK) {
        int i = (b - HBLK) * 256 + tid;
        float w = W[i];
        __nv_bfloat16 h = __float2bfloat16(w);
        g_wh[i] = h;
        g_wl[i] = __float2bfloat16(w - __bfloat162float(h));
    } else {
        if (tid < 32) {
            int acc = 0;
            for (int i = tid; i < 4096; i += 32) acc |= e32[2 * i + 1];
            #pragma unroll
            for (int off = 16; off; off >>= 1) acc |= __shfl_xor_sync(0xFFFFFFFFu, acc, off);
            if (tid == 0) {
                g_stride = acc ? 2 : 4;
                g_doff   = acc ? 1 : 2;
            }
        }
    }
}

// ---------------- K2: per-block exclusive scan ----------------
__global__ __launch_bounds__(256) void scan_block_kernel() {
    int t = threadIdx.x;
    int i = blockIdx.x * 256 + t;
    int lane = t & 31, w = t >> 5;
    int v = (i < O_NUM) ? g_counts[i] : 0;

    int iv = v;
    #pragma unroll
    for (int off = 1; off < 32; off <<= 1) {
        int n = __shfl_up_sync(0xFFFFFFFFu, iv, off);
        if (lane >= off) iv += n;
    }
    __shared__ int ws[8];
    if (lane == 31) ws[w] = iv;
    __syncthreads();
    if (w == 0 && lane < 8) {
        int x = ws[lane];
        #pragma unroll
        for (int off = 1; off < 8; off <<= 1) {
            int n = __shfl_up_sync(0x000000FFu, x, off);
            if (lane >= off) x += n;
        }
        ws[lane] = x;
    }
    __syncthreads();
    int excl = iv - v + (w ? ws[w - 1] : 0);
    if (i < O_NUM) g_offs[i] = excl;
    if (t == 255) g_part[blockIdx.x] = excl + v;
}

// ---------------- K3: fixup + dinv + self-clean counts ----------------
__global__ __launch_bounds__(256) void scan_fix_kernel() {
    int b = blockIdx.x;
    int t = threadIdx.x;
    int lane = t & 31, w = t >> 5;

    int v = (t < b) ? g_part[t] : 0;
    #pragma unroll
    for (int off = 16; off; off >>= 1) v += __shfl_xor_sync(0xFFFFFFFFu, v, off);
    __shared__ int ws[8];
    if (lane == 0) ws[w] = v;
    __syncthreads();
    __shared__ int base_s;
    if (t == 0) {
        int s = 0;
        #pragma unroll
        for (int q = 0; q < 8; q++) s += ws[q];
        base_s = s;
    }
    __syncthreads();
    int base = base_s;

    int i = b * 256 + t;
    if (i < O_NUM) {
        int c = g_counts[i];
        g_offs[i] += base;
        g_dinv[i] = rsqrtf(2.0f + (float)c);
        g_counts[i] = 0;                      // restore invariant for next replay
    }
    if (b == NPART - 1 && t == 0) g_offs[O_NUM] = base + g_part[NPART - 1];
}

// ---------------- K4: easy rows ----------------
__global__ __launch_bounds__(256) void agg_easy_kernel(const float* __restrict__ obj,
                                                       const float* __restrict__ pred,
                                                       const int* __restrict__ e32) {
    int gwarp = (blockIdx.x * blockDim.x + threadIdx.x) >> 5;
    int lane  = threadIdx.x & 31;
    if (gwarp >= T_NUM - O_NUM) return;
    int n = O_NUM + gwarp;

    const float4* xn = reinterpret_cast<const float4*>(pred + (size_t)gwarp * D_DIM);
    float4 a = __ldg(xn + lane);
    int s = edge_src(e32, n, g_stride);
    float ds = g_dinv[s];
    const float4* xs = reinterpret_cast<const float4*>(obj + (size_t)s * D_DIM);
    float4 v = __ldg(xs + lane);

    const float dn = RSQRT2F;
    float4 acc;
    acc.x = (fmaf(v.x, ds, a.x * dn)) * dn;
    acc.y = (fmaf(v.y, ds, a.y * dn)) * dn;
    acc.z = (fmaf(v.z, ds, a.z * dn)) * dn;
    acc.w = (fmaf(v.w, ds, a.w * dn)) * dn;

    float v4[4] = {acc.x, acc.y, acc.z, acc.w};
    alignas(8) __nv_bfloat16 h[4];
    alignas(8) __nv_bfloat16 l[4];
    #pragma unroll
    for (int q = 0; q < 4; q++) {
        h[q] = __float2bfloat16(v4[q]);
        l[q] = __float2bfloat16(v4[q] - __bfloat162float(h[q]));
    }
    size_t base = (size_t)n * D_DIM + lane * 4;
    *reinterpret_cast<uint2*>(g_yh + base) = *reinterpret_cast<const uint2*>(h);
    *reinterpret_cast<uint2*>(g_yl + base) = *reinterpret_cast<const uint2*>(l);
}

// ---------------- K5: counting-sort scatter ----------------
__global__ void csr_scatter_kernel(const int* __restrict__ e32) {
    int t = blockIdx.x * blockDim.x + threadIdx.x;
    if (t < T_NUM) {
        int d = edge_dst(e32, t, g_stride, g_doff);
        int pos = g_offs[d] + atomicAdd(&g_cursor[d], 1);
        g_sorted[pos] = t;
    }
}

// ---------------- K6: hard rows (chain hoisted) + self-clean cursor ----------------
__global__ __launch_bounds__(256) void agg_hard_kernel(const float* __restrict__ obj,
                                                       const float* __restrict__ pred,
                                                       const int* __restrict__ e32) {
    int n = (blockIdx.x * blockDim.x + threadIdx.x) >> 5;
    int lane  = threadIdx.x & 31;
    if (n >= O_NUM) return;

    // start the dependent bucket chain FIRST
    int beg = g_offs[n];
    int cnt = g_offs[n + 1] - beg;
    int m0 = cnt > 8 ? 8 : cnt;
    int   kid0 = 0;
    float dkl0 = 0.0f;
    if (lane < m0) {
        kid0 = g_sorted[beg + lane];
        dkl0 = (kid0 < O_NUM) ? g_dinv[kid0] : RSQRT2F;
    }
    if (lane == 0) g_cursor[n] = 0;           // restore invariant for next replay

    // independent loads issue while the chain resolves
    float dn = g_dinv[n];
    const float4* xn = reinterpret_cast<const float4*>(obj + (size_t)n * D_DIM);
    float4 a = __ldg(xn + lane);
    int s = edge_src(e32, n, g_stride);
    float ds = g_dinv[s];
    const float4* xs = reinterpret_cast<const float4*>(obj + (size_t)s * D_DIM);
    float4 v1 = __ldg(xs + lane);

    float4 acc;
    acc.x = fmaf(v1.x, ds, a.x * dn);
    acc.y = fmaf(v1.y, ds, a.y * dn);
    acc.z = fmaf(v1.z, ds, a.z * dn);
    acc.w = fmaf(v1.w, ds, a.w * dn);

    for (int bb = 0; bb < cnt; bb += 8) {
        int m = cnt - bb; if (m > 8) m = 8;
        int kid; float dkl;
        if (bb == 0) { kid = kid0; dkl = dkl0; }
        else {
            kid = 0; dkl = 0.0f;
            if (lane < m) {
                kid = g_sorted[beg + bb + lane];
                dkl = (kid < O_NUM) ? g_dinv[kid] : RSQRT2F;
            }
        }
        #pragma unroll
        for (int i = 0; i < 8; i++) {
            if (i >= m) break;
            int   k  = __shfl_sync(0xFFFFFFFFu, kid, i);
            float dk = __shfl_sync(0xFFFFFFFFu, dkl, i);
            const float4* xk = reinterpret_cast<const float4*>(row_ptr(k, obj, pred));
            float4 v = __ldg(xk + lane);
            acc.x = fmaf(v.x, dk, acc.x);
            acc.y = fmaf(v.y, dk, acc.y);
            acc.z = fmaf(v.z, dk, acc.z);
            acc.w = fmaf(v.w, dk, acc.w);
        }
    }

    acc.x *= dn; acc.y *= dn; acc.z *= dn; acc.w *= dn;

    float v4[4] = {acc.x, acc.y, acc.z, acc.w};
    alignas(8) __nv_bfloat16 h[4];
    alignas(8) __nv_bfloat16 l[4];
    #pragma unroll
    for (int i = 0; i < 4; i++) {
        h[i] = __float2bfloat16(v4[i]);
        l[i] = __float2bfloat16(v4[i] - __bfloat162float(h[i]));
    }
    size_t base = (size_t)n * D_DIM + lane * 4;
    *reinterpret_cast<uint2*>(g_yh + base) = *reinterpret_cast<const uint2*>(h);
    *reinterpret_cast<uint2*>(g_yl + base) = *reinterpret_cast<const uint2*>(l);
}

// ============ K7: persistent GEMM, W cached in registers (R12-proven) ============
__device__ __forceinline__ void mma16816(float c[4], const uint32_t a[4], const uint32_t b[2]) {
    asm("mma.sync.aligned.m16n8k16.row.col.f32.bf16.bf16.f32 "
        "{%0,%1,%2,%3}, {%4,%5,%6,%7}, {%8,%9}, {%0,%1,%2,%3};"
        : "+f"(c[0]), "+f"(c[1]), "+f"(c[2]), "+f"(c[3])
        : "r"(a[0]), "r"(a[1]), "r"(a[2]), "r"(a[3]), "r"(b[0]), "r"(b[1]));
}

#define LDSY 136
#define TILE_M 32
#define SMEM_W_HALF (128 * LDSY)
#define SMEM_A_HALF (TILE_M * LDSY)
#define GEMM_SMEM_BYTES ((2 * SMEM_W_HALF + 4 * SMEM_A_HALF) * 2)

#define NT_TILES ((N_NUM + TILE_M - 1) / TILE_M)
#define GEMM_GRID 148

__device__ __forceinline__ uint32_t lds32(const __nv_bfloat16* p) {
    return *reinterpret_cast<const uint32_t*>(p);
}
__device__ __forceinline__ void cp_async16(uint32_t dst, const void* src) {
    asm volatile("cp.async.cg.shared.global [%0], [%1], 16;" :: "r"(dst), "l"(src));
}
#define CP_COMMIT() asm volatile("cp.async.commit_group;" ::: "memory")
#define CP_WAIT1()  asm volatile("cp.async.wait_group 1;" ::: "memory")

extern __shared__ char sm_raw[];

__global__ __launch_bounds__(512, 1) void gemm_wreg_kernel(const float* __restrict__ pred,
                                                           const float* __restrict__ bias,
                                                           float* __restrict__ out) {
    __nv_bfloat16* sWh = reinterpret_cast<__nv_bfloat16*>(sm_raw);
    __nv_bfloat16* sWl = sWh + SMEM_W_HALF;
    __nv_bfloat16* sA  = sWl + SMEM_W_HALF;

    int tid  = threadIdx.x;
    int warp = tid >> 5, lane = tid & 31;
    int g  = lane >> 2;
    int tg = lane & 3;
    int band = warp >> 3;
    int cg   = warp & 7;

    #pragma unroll
    for (int it = 0; it < 8; it++) {
        int idx = tid + it * 512;
        int half = idx >> 11;
        int r    = (idx >> 4) & 127;
        int seg  = idx & 15;
        const __nv_bfloat16* src = (half ? g_wl : g_wh) + r * D_DIM + seg * 8;
        __nv_bfloat16* dst = (half ? sWl : sWh) + r * LDSY + seg * 8;
        *reinterpret_cast<uint4*>(dst) = *reinterpret_cast<const uint4*>(src);
    }
    __syncthreads();

    uint32_t wfh[8][2][2], wfl[8][2][2];
    #pragma unroll
    for (int kt = 0; kt < 8; kt++) {
        #pragma unroll
        for (int n = 0; n < 2; n++) {
            int cw = cg * 16 + n * 8 + g;
            const __nv_bfloat16* pH = sWh + cw * LDSY + kt * 16 + tg * 2;
            const __nv_bfloat16* pL = sWl + cw * LDSY + kt * 16 + tg * 2;
            wfh[kt][n][0] = lds32(pH); wfh[kt][n][1] = lds32(pH + 8);
            wfl[kt][n][0] = lds32(pL); wfl[kt][n][1] = lds32(pL + 8);
        }
    }

    float2 bb[2];
    #pragma unroll
    for (int n = 0; n < 2; n++)
        bb[n] = __ldg(reinterpret_cast<const float2*>(bias + cg * 16 + n * 8 + tg * 2));

    uint32_t sA_u32 = (uint32_t)__cvta_generic_to_shared(sA);

    auto stage = [&](int tile, int buf) {
        int rowbase = tile * TILE_M;
        #pragma unroll
        for (int q = 0; q < 2; q++) {
            int idx = tid + q * 512;
            int half = idx >> 9;
            int r    = (idx >> 4) & 31;
            int seg  = idx & 15;
            int grow = rowbase + r;
            uint32_t off = ((buf * 2 + half) * SMEM_A_HALF + r * LDSY + seg * 8) * 2;
            if (grow < T_NUM) {
                const __nv_bfloat16* src = (half ? g_yl : g_yh) + (size_t)grow * D_DIM + seg * 8;
                cp_async16(sA_u32 + off, src);
            } else {
                alignas(16) __nv_bfloat16 v[8];
                if (grow < N_NUM) {
                    const float4* s = reinterpret_cast<const float4*>(
                        pred + (size_t)(grow - O_NUM) * D_DIM + seg * 8);
                    float4 f0 = __ldg(s), f1 = __ldg(s + 1);
                    float ff[8] = {f0.x, f0.y, f0.z, f0.w, f1.x, f1.y, f1.z, f1.w};
                    #pragma unroll
                    for (int p = 0; p < 8; p++) {
                        __nv_bfloat16 hh = __float2bfloat16(ff[p]);
                        v[p] = half ? __float2bfloat16(ff[p] - __bfloat162float(hh)) : hh;
                    }
                } else {
                    #pragma unroll
                    for (int p = 0; p < 8; p++) v[p] = __float2bfloat16(0.f);
                }
                *reinterpret_cast<uint4*>(reinterpret_cast<char*>(sA) + off) =
                    *reinterpret_cast<const uint4*>(v);
            }
        }
    };

    int t0 = blockIdx.x;
    if (t0 < NT_TILES) stage(t0, 0);
    CP_COMMIT();

    int buf = 0;
    for (int t = t0; t < NT_TILES; t += GEMM_GRID) {
        int tn = t + GEMM_GRID;
        if (tn < NT_TILES) stage(tn, buf ^ 1);
        CP_COMMIT();
        CP_WAIT1();
        __syncthreads();

        const __nv_bfloat16* bAh = sA + (buf * 2 + 0) * SMEM_A_HALF;
        const __nv_bfloat16* bAl = sA + (buf * 2 + 1) * SMEM_A_HALF;
        const __nv_bfloat16* aH0 = bAh + (band * 16 + g) * LDSY;
        const __nv_bfloat16* aL0 = bAl + (band * 16 + g) * LDSY;

        float c[2][4];
        #pragma unroll
        for (int n = 0; n < 2; n++)
            #pragma unroll
            for (int q = 0; q < 4; q++) c[n][q] = 0.0f;

        #pragma unroll
        for (int kt = 0; kt < 8; kt++) {
            int k = kt * 16;
            uint32_t ah[4], al[4];
            ah[0] = lds32(aH0 + k + tg * 2);
            ah[1] = lds32(aH0 + 8 * LDSY + k + tg * 2);
            ah[2] = lds32(aH0 + k + 8 + tg * 2);
            ah[3] = lds32(aH0 + 8 * LDSY + k + 8 + tg * 2);
            al[0] = lds32(aL0 + k + tg * 2);
            al[1] = lds32(aL0 + 8 * LDSY + k + tg * 2);
            al[2] = lds32(aL0 + k + 8 + tg * 2);
            al[3] = lds32(aL0 + 8 * LDSY + k + 8 + tg * 2);

            #pragma unroll
            for (int n = 0; n < 2; n++) {
                mma16816(c[n], ah, wfh[kt][n]);
                mma16816(c[n], al, wfh[kt][n]);
                mma16816(c[n], ah, wfl[kt][n]);
            }
        }

        int rowbase = t * TILE_M;
        int r0 = rowbase + band * 16 + g;
        int r1 = r0 + 8;
        #pragma unroll
        for (int n = 0; n < 2; n++) {
            int col = cg * 16 + n * 8 + tg * 2;
            if (r0 < N_NUM) {
                float2 o = make_float2(c[n][0] + bb[n].x, c[n][1] + bb[n].y);
                *reinterpret_cast<float2*>(out + (size_t)r0 * D_DIM + col) = o;
            }
            if (r1 < N_NUM) {
                float2 o = make_float2(c[n][2] + bb[n].x, c[n][3] + bb[n].y);
                *reinterpret_cast<float2*>(out + (size_t)r1 * D_DIM + col) = o;
            }
        }
        buf ^= 1;
        __syncthreads();
    }
}

// ---------------- launch: fork-join (R13 schedule), shorter prefix ----------------
static cudaStream_t g_s2 = nullptr;
static cudaEvent_t  g_evFork = nullptr, g_evJoin = nullptr;

extern "C" void kernel_launch(void* const* d_in, const int* in_sizes, int n_in,
                              void* d_out, int out_size) {
    const float* obj   = (const float*)d_in[0];
    const float* pred  = (const float*)d_in[1];
    const int*   e32   = (const int*)d_in[2];
    const float* W     = (const float*)d_in[3];
    const float* bias  = (const float*)d_in[4];
    float*       out   = (float*)d_out;

    if (g_s2 == nullptr) {
        cudaStreamCreateWithFlags(&g_s2, cudaStreamNonBlocking);
        cudaEventCreateWithFlags(&g_evFork, cudaEventDisableTiming);
        cudaEventCreateWithFlags(&g_evJoin, cudaEventDisableTiming);
        cudaFuncSetAttribute(gemm_wreg_kernel,
                             cudaFuncAttributeMaxDynamicSharedMemorySize, GEMM_SMEM_BYTES);
    }

    // serial prefix (3 launches)
    hist_all_kernel<<<HBLK + WBLK + 1, 256>>>(W, e32);
    scan_block_kernel<<<NPART, 256>>>();
    scan_fix_kernel<<<NPART, 256>>>();

    // fork
    cudaEventRecord(g_evFork, 0);
    cudaStreamWaitEvent(g_s2, g_evFork, 0);

    // branch B (s2): scatter -> hard rows
    csr_scatter_kernel<<<(T_NUM + 255) / 256, 256, 0, g_s2>>>(e32);
    agg_hard_kernel<<<(O_NUM + 7) / 8, 256, 0, g_s2>>>(obj, pred, e32);
    cudaEventRecord(g_evJoin, g_s2);

    // branch A (stream 0): easy rows
    agg_easy_kernel<<<(T_NUM - O_NUM + 7) / 8, 256>>>(obj, pred, e32);

    // join, then full GEMM
    cudaStreamWaitEvent(0, g_evJoin, 0);
    gemm_wreg_kernel<<<GEMM_GRID, 512, GEMM_SMEM_BYTES>>>(pred, bias, out);
}

// round 16
// speedup vs baseline: 1.1410x; 1.1044x over previous
#include <cuda_runtime.h>
#include <cuda_bf16.h>
#include <cstdint>

#define O_NUM 50000
#define T_NUM 200000
#define N_NUM (O_NUM + T_NUM)
#define D_DIM 128
#define NPART 196
#define HBLK  782            // ceil(T_NUM/256)
#define WBLK  64
#define RSQRT2F 0.7071067811865476f

// ---------------- scratch (zero-initialized at module load) ----------------
__device__ __nv_bfloat16 g_yh[(size_t)O_NUM * D_DIM];   // hard rows only
__device__ __nv_bfloat16 g_yl[(size_t)O_NUM * D_DIM];
__device__ __nv_bfloat16 g_wh[D_DIM * D_DIM];
__device__ __nv_bfloat16 g_wl[D_DIM * D_DIM];
__device__ float     g_dinv[O_NUM];
__device__ int       g_counts[O_NUM];   // invariant: zero at call entry (self-cleaning)
__device__ int       g_offs[O_NUM + 1];
__device__ int       g_cursor[O_NUM];   // invariant: zero at call entry (self-cleaning)
__device__ int       g_sorted[T_NUM];
__device__ int       g_part[NPART];
__device__ int       g_stride;
__device__ int       g_doff;

__device__ __forceinline__ int edge_src(const int* e32, int t, int stride) {
    return __ldg(e32 + (size_t)stride * t);
}
__device__ __forceinline__ int edge_dst(const int* e32, int t, int stride, int doff) {
    return __ldg(e32 + (size_t)stride * t + doff);
}
__device__ __forceinline__ const float* row_ptr(int k, const float* obj, const float* pred) {
    return (k < O_NUM) ? (obj + (size_t)k * D_DIM) : (pred + (size_t)(k - O_NUM) * D_DIM);
}

// ---------------- K1: hist + W split + global dtype detect ----------------
__global__ void hist_all_kernel(const float* __restrict__ W, const int* __restrict__ e32) {
    int b = blockIdx.x;
    int tid = threadIdx.x;
    if (b < HBLK) {
        int idx = 512 * b + 2 * tid + 1;
        int v = (idx < 2 * T_NUM) ? e32[idx] : 0;
        int any = __syncthreads_or(v);
        int stride = any ? 2 : 4;
        int doff   = any ? 1 : 2;
        int t = b * 256 + tid;
        if (t < T_NUM) {
            int d = e32[(size_t)stride * t + doff];
            atomicAdd(&g_counts[d], 1);
        }
    } else if (b < HBLK + WBLK) {
        int i = (b - HBLK) * 256 + tid;
        float w = W[i];
        __nv_bfloat16 h = __float2bfloat16(w);
        g_wh[i] = h;
        g_wl[i] = __float2bfloat16(w - __bfloat162float(h));
    } else {
        if (tid < 32) {
            int acc = 0;
            for (int i = tid; i < 4096; i += 32) acc |= e32[2 * i + 1];
            #pragma unroll
            for (int off = 16; off; off >>= 1) acc |= __shfl_xor_sync(0xFFFFFFFFu, acc, off);
            if (tid == 0) {
                g_stride = acc ? 2 : 4;
                g_doff   = acc ? 1 : 2;
            }
        }
    }
}

// ---------------- K2: per-block exclusive scan ----------------
__global__ __launch_bounds__(256) void scan_block_kernel() {
    int t = threadIdx.x;
    int i = blockIdx.x * 256 + t;
    int lane = t & 31, w = t >> 5;
    int v = (i < O_NUM) ? g_counts[i] : 0;

    int iv = v;
    #pragma unroll
    for (int off = 1; off < 32; off <<= 1) {
        int n = __shfl_up_sync(0xFFFFFFFFu, iv, off);
        if (lane >= off) iv += n;
    }
    __shared__ int ws[8];
    if (lane == 31) ws[w] = iv;
    __syncthreads();
    if (w == 0 && lane < 8) {
        int x = ws[lane];
        #pragma unroll
        for (int off = 1; off < 8; off <<= 1) {
            int n = __shfl_up_sync(0x000000FFu, x, off);
            if (lane >= off) x += n;
        }
        ws[lane] = x;
    }
    __syncthreads();
    int excl = iv - v + (w ? ws[w - 1] : 0);
    if (i < O_NUM) g_offs[i] = excl;
    if (t == 255) g_part[blockIdx.x] = excl + v;
}

// ---------------- K3: fixup + dinv + self-clean counts ----------------
__global__ __launch_bounds__(256) void scan_fix_kernel() {
    int b = blockIdx.x;
    int t = threadIdx.x;
    int lane = t & 31, w = t >> 5;

    int v = (t < b) ? g_part[t] : 0;
    #pragma unroll
    for (int off = 16; off; off >>= 1) v += __shfl_xor_sync(0xFFFFFFFFu, v, off);
    __shared__ int ws[8];
    if (lane == 0) ws[w] = v;
    __syncthreads();
    __shared__ int base_s;
    if (t == 0) {
        int s = 0;
        #pragma unroll
        for (int q = 0; q < 8; q++) s += ws[q];
        base_s = s;
    }
    __syncthreads();
    int base = base_s;

    int i = b * 256 + t;
    if (i < O_NUM) {
        int c = g_counts[i];
        g_offs[i] += base;
        g_dinv[i] = rsqrtf(2.0f + (float)c);
        g_counts[i] = 0;
    }
    if (b == NPART - 1 && t == 0) g_offs[O_NUM] = base + g_part[NPART - 1];
}

// ---------------- K4: counting-sort scatter ----------------
__global__ void csr_scatter_kernel(const int* __restrict__ e32) {
    int t = blockIdx.x * blockDim.x + threadIdx.x;
    if (t < T_NUM) {
        int d = edge_dst(e32, t, g_stride, g_doff);
        int pos = g_offs[d] + atomicAdd(&g_cursor[d], 1);
        g_sorted[pos] = t;
    }
}

// ---------------- K5: hard rows (chain hoisted) + self-clean cursor ----------------
__global__ __launch_bounds__(256) void agg_hard_kernel(const float* __restrict__ obj,
                                                       const float* __restrict__ pred,
                                                       const int* __restrict__ e32) {
    int n = (blockIdx.x * blockDim.x + threadIdx.x) >> 5;
    int lane  = threadIdx.x & 31;
    if (n >= O_NUM) return;

    int beg = g_offs[n];
    int cnt = g_offs[n + 1] - beg;
    int m0 = cnt > 8 ? 8 : cnt;
    int   kid0 = 0;
    float dkl0 = 0.0f;
    if (lane < m0) {
        kid0 = g_sorted[beg + lane];
        dkl0 = (kid0 < O_NUM) ? g_dinv[kid0] : RSQRT2F;
    }
    if (lane == 0) g_cursor[n] = 0;

    float dn = g_dinv[n];
    const float4* xn = reinterpret_cast<const float4*>(obj + (size_t)n * D_DIM);
    float4 a = __ldg(xn + lane);
    int s = edge_src(e32, n, g_stride);
    float ds = g_dinv[s];
    const float4* xs = reinterpret_cast<const float4*>(obj + (size_t)s * D_DIM);
    float4 v1 = __ldg(xs + lane);

    float4 acc;
    acc.x = fmaf(v1.x, ds, a.x * dn);
    acc.y = fmaf(v1.y, ds, a.y * dn);
    acc.z = fmaf(v1.z, ds, a.z * dn);
    acc.w = fmaf(v1.w, ds, a.w * dn);

    for (int bb = 0; bb < cnt; bb += 8) {
        int m = cnt - bb; if (m > 8) m = 8;
        int kid; float dkl;
        if (bb == 0) { kid = kid0; dkl = dkl0; }
        else {
            kid = 0; dkl = 0.0f;
            if (lane < m) {
                kid = g_sorted[beg + bb + lane];
                dkl = (kid < O_NUM) ? g_dinv[kid] : RSQRT2F;
            }
        }
        #pragma unroll
        for (int i = 0; i < 8; i++) {
            if (i >= m) break;
            int   k  = __shfl_sync(0xFFFFFFFFu, kid, i);
            float dk = __shfl_sync(0xFFFFFFFFu, dkl, i);
            const float4* xk = reinterpret_cast<const float4*>(row_ptr(k, obj, pred));
            float4 v = __ldg(xk + lane);
            acc.x = fmaf(v.x, dk, acc.x);
            acc.y = fmaf(v.y, dk, acc.y);
            acc.z = fmaf(v.z, dk, acc.z);
            acc.w = fmaf(v.w, dk, acc.w);
        }
    }

    acc.x *= dn; acc.y *= dn; acc.z *= dn; acc.w *= dn;

    float v4[4] = {acc.x, acc.y, acc.z, acc.w};
    alignas(8) __nv_bfloat16 h[4];
    alignas(8) __nv_bfloat16 l[4];
    #pragma unroll
    for (int i = 0; i < 4; i++) {
        h[i] = __float2bfloat16(v4[i]);
        l[i] = __float2bfloat16(v4[i] - __bfloat162float(h[i]));
    }
    size_t base = (size_t)n * D_DIM + lane * 4;
    *reinterpret_cast<uint2*>(g_yh + base) = *reinterpret_cast<const uint2*>(h);
    *reinterpret_cast<uint2*>(g_yl + base) = *reinterpret_cast<const uint2*>(l);
}

// ============ K6: persistent GEMM with fused easy-row staging ============
__device__ __forceinline__ void mma16816(float c[4], const uint32_t a[4], const uint32_t b[2]) {
    asm("mma.sync.aligned.m16n8k16.row.col.f32.bf16.bf16.f32 "
        "{%0,%1,%2,%3}, {%4,%5,%6,%7}, {%8,%9}, {%0,%1,%2,%3};"
        : "+f"(c[0]), "+f"(c[1]), "+f"(c[2]), "+f"(c[3])
        : "r"(a[0]), "r"(a[1]), "r"(a[2]), "r"(a[3]), "r"(b[0]), "r"(b[1]));
}

#define LDSY 136
#define TILE_M 32
#define SMEM_W_HALF (128 * LDSY)
#define SMEM_A_HALF (TILE_M * LDSY)
#define GEMM_SMEM_BYTES ((2 * SMEM_W_HALF + 4 * SMEM_A_HALF) * 2)

#define NT_TILES ((N_NUM + TILE_M - 1) / TILE_M)    // 7813
#define TILE_LOW_END 1563                            // tiles [0,1563): rows 0..50015
#define GEMM_GRID 148

__device__ __forceinline__ uint32_t lds32(const __nv_bfloat16* p) {
    return *reinterpret_cast<const uint32_t*>(p);
}
__device__ __forceinline__ void cp_async16(uint32_t dst, const void* src) {
    asm volatile("cp.async.cg.shared.global [%0], [%1], 16;" :: "r"(dst), "l"(src));
}
#define CP_COMMIT() asm volatile("cp.async.commit_group;" ::: "memory")
#define CP_WAIT1()  asm volatile("cp.async.wait_group 1;" ::: "memory")

extern __shared__ char sm_raw[];

__global__ __launch_bounds__(512, 1) void gemm_fused_kernel(const float* __restrict__ obj,
                                                            const float* __restrict__ pred,
                                                            const int* __restrict__ e32,
                                                            const float* __restrict__ bias,
                                                            float* __restrict__ out,
                                                            int t_begin, int t_end) {
    __nv_bfloat16* sWh = reinterpret_cast<__nv_bfloat16*>(sm_raw);
    __nv_bfloat16* sWl = sWh + SMEM_W_HALF;
    __nv_bfloat16* sA  = sWl + SMEM_W_HALF;

    int tid  = threadIdx.x;
    int warp = tid >> 5, lane = tid & 31;
    int g  = lane >> 2;
    int tg = lane & 3;
    int band = warp >> 3;
    int cg   = warp & 7;
    int stride = g_stride;

    // W staging into smem
    #pragma unroll
    for (int it = 0; it < 8; it++) {
        int idx = tid + it * 512;
        int half = idx >> 11;
        int r    = (idx >> 4) & 127;
        int seg  = idx & 15;
        const __nv_bfloat16* src = (half ? g_wl : g_wh) + r * D_DIM + seg * 8;
        __nv_bfloat16* dst = (half ? sWl : sWh) + r * LDSY + seg * 8;
        *reinterpret_cast<uint4*>(dst) = *reinterpret_cast<const uint4*>(src);
    }
    __syncthreads();

    // W fragments into registers
    uint32_t wfh[8][2][2], wfl[8][2][2];
    #pragma unroll
    for (int kt = 0; kt < 8; kt++) {
        #pragma unroll
        for (int n = 0; n < 2; n++) {
            int cw = cg * 16 + n * 8 + g;
            const __nv_bfloat16* pH = sWh + cw * LDSY + kt * 16 + tg * 2;
            const __nv_bfloat16* pL = sWl + cw * LDSY + kt * 16 + tg * 2;
            wfh[kt][n][0] = lds32(pH); wfh[kt][n][1] = lds32(pH + 8);
            wfl[kt][n][0] = lds32(pL); wfl[kt][n][1] = lds32(pL + 8);
        }
    }

    float2 bb[2];
    #pragma unroll
    for (int n = 0; n < 2; n++)
        bb[n] = __ldg(reinterpret_cast<const float2*>(bias + cg * 16 + n * 8 + tg * 2));

    uint32_t sA_u32 = (uint32_t)__cvta_generic_to_shared(sA);

    // staging: thread handles row r = tid>>4, segment seg = tid&15 (8 floats)
    int srow = tid >> 4;
    int sseg = tid & 15;

    // pipeline registers
    float4 p0, p1, q0, q1;
    float pds, pdn;
    int pmode;   // 0 = cp.async (hard row), 1 = fused compute

    auto stage_load = [&](int tile, int buf) {
        int grow = tile * TILE_M + srow;
        if (grow < O_NUM) {
            uint32_t hi_off = ((buf * 2 + 0) * SMEM_A_HALF + srow * LDSY + sseg * 8) * 2;
            uint32_t lo_off = ((buf * 2 + 1) * SMEM_A_HALF + srow * LDSY + sseg * 8) * 2;
            cp_async16(sA_u32 + hi_off, g_yh + (size_t)grow * D_DIM + sseg * 8);
            cp_async16(sA_u32 + lo_off, g_yl + (size_t)grow * D_DIM + sseg * 8);
            pmode = 0;
        } else {
            pmode = 1;
            p0 = p1 = q0 = q1 = make_float4(0.f, 0.f, 0.f, 0.f);
            pds = 0.0f; pdn = 1.0f;
            if (grow < N_NUM) {
                const float4* pa = reinterpret_cast<const float4*>(
                    pred + (size_t)(grow - O_NUM) * D_DIM + sseg * 8);
                p0 = __ldg(pa); p1 = __ldg(pa + 1);
                if (grow < T_NUM) {
                    int s = edge_src(e32, grow, stride);
                    pds = g_dinv[s];
                    const float4* pv = reinterpret_cast<const float4*>(
                        obj + (size_t)s * D_DIM + sseg * 8);
                    q0 = __ldg(pv); q1 = __ldg(pv + 1);
                    pdn = RSQRT2F;
                }
            }
        }
    };

    auto stage_store = [&](int buf) {
        if (pmode != 1) return;
        float pa[8] = {p0.x, p0.y, p0.z, p0.w, p1.x, p1.y, p1.z, p1.w};
        float pv[8] = {q0.x, q0.y, q0.z, q0.w, q1.x, q1.y, q1.z, q1.w};
        alignas(16) __nv_bfloat16 h[8], l[8];
        #pragma unroll
        for (int p = 0; p < 8; p++) {
            float y = (fmaf(pv[p], pds, pa[p] * pdn)) * pdn;
            h[p] = __float2bfloat16(y);
            l[p] = __float2bfloat16(y - __bfloat162float(h[p]));
        }
        uint32_t hi_off = ((buf * 2 + 0) * SMEM_A_HALF + srow * LDSY + sseg * 8) * 2;
        uint32_t lo_off = ((buf * 2 + 1) * SMEM_A_HALF + srow * LDSY + sseg * 8) * 2;
        *reinterpret_cast<uint4*>(reinterpret_cast<char*>(sA) + hi_off) =
            *reinterpret_cast<const uint4*>(h);
        *reinterpret_cast<uint4*>(reinterpret_cast<char*>(sA) + lo_off) =
            *reinterpret_cast<const uint4*>(l);
    };

    int t0 = t_begin + blockIdx.x;
    if (t0 < t_end) {
        stage_load(t0, 0);
        CP_COMMIT();
        stage_store(0);
    } else {
        CP_COMMIT();
    }

    int buf = 0;
    for (int t = t0; t < t_end; t += GEMM_GRID) {
        int tn = t + GEMM_GRID;
        bool have_next = tn < t_end;
        if (have_next) stage_load(tn, buf ^ 1);    // loads resolve under MMA below
        CP_COMMIT();
        CP_WAIT1();                                 // tile t's async data ready
        __syncthreads();

        const __nv_bfloat16* bAh = sA + (buf * 2 + 0) * SMEM_A_HALF;
        const __nv_bfloat16* bAl = sA + (buf * 2 + 1) * SMEM_A_HALF;
        const __nv_bfloat16* aH0 = bAh + (band * 16 + g) * LDSY;
        const __nv_bfloat16* aL0 = bAl + (band * 16 + g) * LDSY;

        float c[2][4];
        #pragma unroll
        for (int n = 0; n < 2; n++)
            #pragma unroll
            for (int q = 0; q < 4; q++) c[n][q] = 0.0f;

        #pragma unroll
        for (int kt = 0; kt < 8; kt++) {
            int k = kt * 16;
            uint32_t ah[4], al[4];
            ah[0] = lds32(aH0 + k + tg * 2);
            ah[1] = lds32(aH0 + 8 * LDSY + k + tg * 2);
            ah[2] = lds32(aH0 + k + 8 + tg * 2);
            ah[3] = lds32(aH0 + 8 * LDSY + k + 8 + tg * 2);
            al[0] = lds32(aL0 + k + tg * 2);
            al[1] = lds32(aL0 + 8 * LDSY + k + tg * 2);
            al[2] = lds32(aL0 + k + 8 + tg * 2);
            al[3] = lds32(aL0 + 8 * LDSY + k + 8 + tg * 2);

            #pragma unroll
            for (int n = 0; n < 2; n++) {
                mma16816(c[n], ah, wfh[kt][n]);
                mma16816(c[n], al, wfh[kt][n]);
                mma16816(c[n], ah, wfl[kt][n]);
            }
        }

        int rowbase = t * TILE_M;
        int r0 = rowbase + band * 16 + g;
        int r1 = r0 + 8;
        #pragma unroll
        for (int n = 0; n < 2; n++) {
            int col = cg * 16 + n * 8 + tg * 2;
            if (r0 < N_NUM) {
                float2 o = make_float2(c[n][0] + bb[n].x, c[n][1] + bb[n].y);
                *reinterpret_cast<float2*>(out + (size_t)r0 * D_DIM + col) = o;
            }
            if (r1 < N_NUM) {
                float2 o = make_float2(c[n][2] + bb[n].x, c[n][3] + bb[n].y);
                *reinterpret_cast<float2*>(out + (size_t)r1 * D_DIM + col) = o;
            }
        }

        if (have_next) stage_store(buf ^ 1);        // fused rows: regs -> smem
        buf ^= 1;
        __syncthreads();
    }
}

// ---------------- launch ----------------
static cudaStream_t g_s2 = nullptr;
static cudaEvent_t  g_evFork = nullptr, g_evJoin = nullptr;

extern "C" void kernel_launch(void* const* d_in, const int* in_sizes, int n_in,
                              void* d_out, int out_size) {
    const float* obj   = (const float*)d_in[0];
    const float* pred  = (const float*)d_in[1];
    const int*   e32   = (const int*)d_in[2];
    const float* W     = (const float*)d_in[3];
    const float* bias  = (const float*)d_in[4];
    float*       out   = (float*)d_out;

    if (g_s2 == nullptr) {
        cudaStreamCreateWithFlags(&g_s2, cudaStreamNonBlocking);
        cudaEventCreateWithFlags(&g_evFork, cudaEventDisableTiming);
        cudaEventCreateWithFlags(&g_evJoin, cudaEventDisableTiming);
        cudaFuncSetAttribute(gemm_fused_kernel,
                             cudaFuncAttributeMaxDynamicSharedMemorySize, GEMM_SMEM_BYTES);
    }

    // serial prefix
    hist_all_kernel<<<HBLK + WBLK + 1, 256>>>(W, e32);
    scan_block_kernel<<<NPART, 256>>>();
    scan_fix_kernel<<<NPART, 256>>>();

    // fork
    cudaEventRecord(g_evFork, 0);
    cudaStreamWaitEvent(g_s2, g_evFork, 0);

    // branch B (s2): scatter -> hard rows
    csr_scatter_kernel<<<(T_NUM + 255) / 256, 256, 0, g_s2>>>(e32);
    agg_hard_kernel<<<(O_NUM + 7) / 8, 256, 0, g_s2>>>(obj, pred, e32);
    cudaEventRecord(g_evJoin, g_s2);

    // branch A (stream 0): GEMM over rows >= 50016 (easy fused inline + identity)
    gemm_fused_kernel<<<GEMM_GRID, 512, GEMM_SMEM_BYTES>>>(obj, pred, e32, bias, out,
                                                           TILE_LOW_END, NT_TILES);

    // join, then GEMM over rows 0..50015 (hard rows via Yh/Yl + 16 fused easy rows)
    cudaStreamWaitEvent(0, g_evJoin, 0);
    gemm_fused_kernel<<<GEMM_GRID, 512, GEMM_SMEM_BYTES>>>(obj, pred, e32, bias, out,
                                                           0, TILE_LOW_END);
}

// round 17
// speedup vs baseline: 1.1618x; 1.0182x over previous
#include <cuda_runtime.h>
#include <cuda_bf16.h>
#include <cstdint>

#define O_NUM 50000
#define T_NUM 200000
#define N_NUM (O_NUM + T_NUM)
#define D_DIM 128
#define NPART 196
#define HBLK  782            // ceil(T_NUM/256)
#define RSQRT2F 0.7071067811865476f

// ---------------- scratch (zero-initialized at module load) ----------------
__device__ __nv_bfloat16 g_yh[(size_t)O_NUM * D_DIM];   // hard rows only
__device__ __nv_bfloat16 g_yl[(size_t)O_NUM * D_DIM];
__device__ float     g_dinv[O_NUM];
__device__ int       g_counts[O_NUM];   // invariant: zero at call entry (self-cleaning)
__device__ int       g_offs[O_NUM + 1];
__device__ int       g_cursor[O_NUM];   // invariant: zero at call entry (self-cleaning)
__device__ int       g_sorted[T_NUM];
__device__ int       g_part[NPART];
__device__ int       g_stride;
__device__ int       g_doff;

__device__ __forceinline__ int edge_src(const int* e32, int t, int stride) {
    return __ldg(e32 + (size_t)stride * t);
}
__device__ __forceinline__ int edge_dst(const int* e32, int t, int stride, int doff) {
    return __ldg(e32 + (size_t)stride * t + doff);
}
__device__ __forceinline__ const float* row_ptr(int k, const float* obj, const float* pred) {
    return (k < O_NUM) ? (obj + (size_t)k * D_DIM) : (pred + (size_t)(k - O_NUM) * D_DIM);
}

// ---------------- K1: hist + global dtype detect ----------------
__global__ void hist_all_kernel(const int* __restrict__ e32) {
    int b = blockIdx.x;
    int tid = threadIdx.x;
    if (b < HBLK) {
        int idx = 512 * b + 2 * tid + 1;
        int v = (idx < 2 * T_NUM) ? e32[idx] : 0;
        int any = __syncthreads_or(v);
        int stride = any ? 2 : 4;
        int doff   = any ? 1 : 2;
        int t = b * 256 + tid;
        if (t < T_NUM) {
            int d = e32[(size_t)stride * t + doff];
            atomicAdd(&g_counts[d], 1);
        }
    } else {
        if (tid < 32) {
            int acc = 0;
            for (int i = tid; i < 4096; i += 32) acc |= e32[2 * i + 1];
            #pragma unroll
            for (int off = 16; off; off >>= 1) acc |= __shfl_xor_sync(0xFFFFFFFFu, acc, off);
            if (tid == 0) {
                g_stride = acc ? 2 : 4;
                g_doff   = acc ? 1 : 2;
            }
        }
    }
}

// ---------------- K2: per-block exclusive scan ----------------
__global__ __launch_bounds__(256) void scan_block_kernel() {
    int t = threadIdx.x;
    int i = blockIdx.x * 256 + t;
    int lane = t & 31, w = t >> 5;
    int v = (i < O_NUM) ? g_counts[i] : 0;

    int iv = v;
    #pragma unroll
    for (int off = 1; off < 32; off <<= 1) {
        int n = __shfl_up_sync(0xFFFFFFFFu, iv, off);
        if (lane >= off) iv += n;
    }
    __shared__ int ws[8];
    if (lane == 31) ws[w] = iv;
    __syncthreads();
    if (w == 0 && lane < 8) {
        int x = ws[lane];
        #pragma unroll
        for (int off = 1; off < 8; off <<= 1) {
            int n = __shfl_up_sync(0x000000FFu, x, off);
            if (lane >= off) x += n;
        }
        ws[lane] = x;
    }
    __syncthreads();
    int excl = iv - v + (w ? ws[w - 1] : 0);
    if (i < O_NUM) g_offs[i] = excl;
    if (t == 255) g_part[blockIdx.x] = excl + v;
}

// ---------------- K3: fixup + dinv + self-clean counts ----------------
__global__ __launch_bounds__(256) void scan_fix_kernel() {
    int b = blockIdx.x;
    int t = threadIdx.x;
    int lane = t & 31, w = t >> 5;

    int v = (t < b) ? g_part[t] : 0;
    #pragma unroll
    for (int off = 16; off; off >>= 1) v += __shfl_xor_sync(0xFFFFFFFFu, v, off);
    __shared__ int ws[8];
    if (lane == 0) ws[w] = v;
    __syncthreads();
    __shared__ int base_s;
    if (t == 0) {
        int s = 0;
        #pragma unroll
        for (int q = 0; q < 8; q++) s += ws[q];
        base_s = s;
    }
    __syncthreads();
    int base = base_s;

    int i = b * 256 + t;
    if (i < O_NUM) {
        int c = g_counts[i];
        g_offs[i] += base;
        g_dinv[i] = rsqrtf(2.0f + (float)c);
        g_counts[i] = 0;
    }
    if (b == NPART - 1 && t == 0) g_offs[O_NUM] = base + g_part[NPART - 1];
}

// ---------------- K4: counting-sort scatter ----------------
__global__ void csr_scatter_kernel(const int* __restrict__ e32) {
    int t = blockIdx.x * blockDim.x + threadIdx.x;
    if (t < T_NUM) {
        int d = edge_dst(e32, t, g_stride, g_doff);
        int pos = g_offs[d] + atomicAdd(&g_cursor[d], 1);
        g_sorted[pos] = t;
    }
}

// ---------------- K5: hard rows (chain hoisted) + self-clean cursor ----------------
__global__ __launch_bounds__(256) void agg_hard_kernel(const float* __restrict__ obj,
                                                       const float* __restrict__ pred,
                                                       const int* __restrict__ e32) {
    int n = (blockIdx.x * blockDim.x + threadIdx.x) >> 5;
    int lane  = threadIdx.x & 31;
    if (n >= O_NUM) return;

    int beg = g_offs[n];
    int cnt = g_offs[n + 1] - beg;
    int m0 = cnt > 8 ? 8 : cnt;
    int   kid0 = 0;
    float dkl0 = 0.0f;
    if (lane < m0) {
        kid0 = g_sorted[beg + lane];
        dkl0 = (kid0 < O_NUM) ? g_dinv[kid0] : RSQRT2F;
    }
    if (lane == 0) g_cursor[n] = 0;

    float dn = g_dinv[n];
    const float4* xn = reinterpret_cast<const float4*>(obj + (size_t)n * D_DIM);
    float4 a = __ldg(xn + lane);
    int s = edge_src(e32, n, g_stride);
    float ds = g_dinv[s];
    const float4* xs = reinterpret_cast<const float4*>(obj + (size_t)s * D_DIM);
    float4 v1 = __ldg(xs + lane);

    float4 acc;
    acc.x = fmaf(v1.x, ds, a.x * dn);
    acc.y = fmaf(v1.y, ds, a.y * dn);
    acc.z = fmaf(v1.z, ds, a.z * dn);
    acc.w = fmaf(v1.w, ds, a.w * dn);

    for (int bb = 0; bb < cnt; bb += 8) {
        int m = cnt - bb; if (m > 8) m = 8;
        int kid; float dkl;
        if (bb == 0) { kid = kid0; dkl = dkl0; }
        else {
            kid = 0; dkl = 0.0f;
            if (lane < m) {
                kid = g_sorted[beg + bb + lane];
                dkl = (kid < O_NUM) ? g_dinv[kid] : RSQRT2F;
            }
        }
        #pragma unroll
        for (int i = 0; i < 8; i++) {
            if (i >= m) break;
            int   k  = __shfl_sync(0xFFFFFFFFu, kid, i);
            float dk = __shfl_sync(0xFFFFFFFFu, dkl, i);
            const float4* xk = reinterpret_cast<const float4*>(row_ptr(k, obj, pred));
            float4 v = __ldg(xk + lane);
            acc.x = fmaf(v.x, dk, acc.x);
            acc.y = fmaf(v.y, dk, acc.y);
            acc.z = fmaf(v.z, dk, acc.z);
            acc.w = fmaf(v.w, dk, acc.w);
        }
    }

    acc.x *= dn; acc.y *= dn; acc.z *= dn; acc.w *= dn;

    float v4[4] = {acc.x, acc.y, acc.z, acc.w};
    alignas(8) __nv_bfloat16 h[4];
    alignas(8) __nv_bfloat16 l[4];
    #pragma unroll
    for (int i = 0; i < 4; i++) {
        h[i] = __float2bfloat16(v4[i]);
        l[i] = __float2bfloat16(v4[i] - __bfloat162float(h[i]));
    }
    size_t base = (size_t)n * D_DIM + lane * 4;
    *reinterpret_cast<uint2*>(g_yh + base) = *reinterpret_cast<const uint2*>(h);
    *reinterpret_cast<uint2*>(g_yl + base) = *reinterpret_cast<const uint2*>(l);
}

// ============ K6: persistent GEMM, self-split W, fused easy staging ============
__device__ __forceinline__ void mma16816(float c[4], const uint32_t a[4], const uint32_t b[2]) {
    asm("mma.sync.aligned.m16n8k16.row.col.f32.bf16.bf16.f32 "
        "{%0,%1,%2,%3}, {%4,%5,%6,%7}, {%8,%9}, {%0,%1,%2,%3};"
        : "+f"(c[0]), "+f"(c[1]), "+f"(c[2]), "+f"(c[3])
        : "r"(a[0]), "r"(a[1]), "r"(a[2]), "r"(a[3]), "r"(b[0]), "r"(b[1]));
}

#define LDSY 136
#define TILE_M 32
#define SMEM_W_HALF (128 * LDSY)
#define SMEM_A_HALF (TILE_M * LDSY)
#define GEMM_SMEM_BYTES ((2 * SMEM_W_HALF + 4 * SMEM_A_HALF) * 2)

#define NT_TILES ((N_NUM + TILE_M - 1) / TILE_M)    // 7813
#define TILE_LOW_END 1563                            // rows 0..50015
#define TILE_ID_BEGIN (T_NUM / TILE_M)               // 6250: rows >= 200000
#define GEMM_GRID 148

__device__ __forceinline__ uint32_t lds32(const __nv_bfloat16* p) {
    return *reinterpret_cast<const uint32_t*>(p);
}
__device__ __forceinline__ void cp_async16(uint32_t dst, const void* src) {
    asm volatile("cp.async.cg.shared.global [%0], [%1], 16;" :: "r"(dst), "l"(src));
}
#define CP_COMMIT() asm volatile("cp.async.commit_group;" ::: "memory")
#define CP_WAIT1()  asm volatile("cp.async.wait_group 1;" ::: "memory")

extern __shared__ char sm_raw[];

__global__ __launch_bounds__(512, 1) void gemm_fused_kernel(const float* __restrict__ obj,
                                                            const float* __restrict__ pred,
                                                            const int* __restrict__ e32,
                                                            const float* __restrict__ W,
                                                            const float* __restrict__ bias,
                                                            float* __restrict__ out,
                                                            int t_begin, int t_end) {
    __nv_bfloat16* sWh = reinterpret_cast<__nv_bfloat16*>(sm_raw);
    __nv_bfloat16* sWl = sWh + SMEM_W_HALF;
    __nv_bfloat16* sA  = sWl + SMEM_W_HALF;

    int tid  = threadIdx.x;
    int warp = tid >> 5, lane = tid & 31;
    int g  = lane >> 2;
    int tg = lane & 3;
    int band = warp >> 3;
    int cg   = warp & 7;
    int stride = g_stride;

    // W staging: self-split fp32 -> bf16 hi/lo in smem (no external dependency)
    #pragma unroll
    for (int it = 0; it < 4; it++) {
        int idx = tid + it * 512;           // 0..2047 chunks of 8 floats
        int r   = idx >> 4;
        int seg = idx & 15;
        const float4* s = reinterpret_cast<const float4*>(W + (size_t)r * D_DIM + seg * 8);
        float4 f0 = __ldg(s), f1 = __ldg(s + 1);
        float ff[8] = {f0.x, f0.y, f0.z, f0.w, f1.x, f1.y, f1.z, f1.w};
        alignas(16) __nv_bfloat16 h[8], l[8];
        #pragma unroll
        for (int p = 0; p < 8; p++) {
            h[p] = __float2bfloat16(ff[p]);
            l[p] = __float2bfloat16(ff[p] - __bfloat162float(h[p]));
        }
        *reinterpret_cast<uint4*>(sWh + r * LDSY + seg * 8) = *reinterpret_cast<const uint4*>(h);
        *reinterpret_cast<uint4*>(sWl + r * LDSY + seg * 8) = *reinterpret_cast<const uint4*>(l);
    }
    __syncthreads();

    // W fragments into registers
    uint32_t wfh[8][2][2], wfl[8][2][2];
    #pragma unroll
    for (int kt = 0; kt < 8; kt++) {
        #pragma unroll
        for (int n = 0; n < 2; n++) {
            int cw = cg * 16 + n * 8 + g;
            const __nv_bfloat16* pH = sWh + cw * LDSY + kt * 16 + tg * 2;
            const __nv_bfloat16* pL = sWl + cw * LDSY + kt * 16 + tg * 2;
            wfh[kt][n][0] = lds32(pH); wfh[kt][n][1] = lds32(pH + 8);
            wfl[kt][n][0] = lds32(pL); wfl[kt][n][1] = lds32(pL + 8);
        }
    }

    float2 bb[2];
    #pragma unroll
    for (int n = 0; n < 2; n++)
        bb[n] = __ldg(reinterpret_cast<const float2*>(bias + cg * 16 + n * 8 + tg * 2));

    uint32_t sA_u32 = (uint32_t)__cvta_generic_to_shared(sA);

    int srow = tid >> 4;
    int sseg = tid & 15;

    float4 p0, p1, q0, q1;
    float pds, pdn;
    int pmode;

    auto stage_load = [&](int tile, int buf) {
        int grow = tile * TILE_M + srow;
        if (grow < O_NUM) {
            uint32_t hi_off = ((buf * 2 + 0) * SMEM_A_HALF + srow * LDSY + sseg * 8) * 2;
            uint32_t lo_off = ((buf * 2 + 1) * SMEM_A_HALF + srow * LDSY + sseg * 8) * 2;
            cp_async16(sA_u32 + hi_off, g_yh + (size_t)grow * D_DIM + sseg * 8);
            cp_async16(sA_u32 + lo_off, g_yl + (size_t)grow * D_DIM + sseg * 8);
            pmode = 0;
        } else {
            pmode = 1;
            p0 = p1 = q0 = q1 = make_float4(0.f, 0.f, 0.f, 0.f);
            pds = 0.0f; pdn = 1.0f;
            if (grow < N_NUM) {
                const float4* pa = reinterpret_cast<const float4*>(
                    pred + (size_t)(grow - O_NUM) * D_DIM + sseg * 8);
                p0 = __ldg(pa); p1 = __ldg(pa + 1);
                if (grow < T_NUM) {
                    int s = edge_src(e32, grow, stride);
                    pds = g_dinv[s];
                    const float4* pv = reinterpret_cast<const float4*>(
                        obj + (size_t)s * D_DIM + sseg * 8);
                    q0 = __ldg(pv); q1 = __ldg(pv + 1);
                    pdn = RSQRT2F;
                }
            }
        }
    };

    auto stage_store = [&](int buf) {
        if (pmode != 1) return;
        float pa[8] = {p0.x, p0.y, p0.z, p0.w, p1.x, p1.y, p1.z, p1.w};
        float pv[8] = {q0.x, q0.y, q0.z, q0.w, q1.x, q1.y, q1.z, q1.w};
        alignas(16) __nv_bfloat16 h[8], l[8];
        #pragma unroll
        for (int p = 0; p < 8; p++) {
            float y = (fmaf(pv[p], pds, pa[p] * pdn)) * pdn;
            h[p] = __float2bfloat16(y);
            l[p] = __float2bfloat16(y - __bfloat162float(h[p]));
        }
        uint32_t hi_off = ((buf * 2 + 0) * SMEM_A_HALF + srow * LDSY + sseg * 8) * 2;
        uint32_t lo_off = ((buf * 2 + 1) * SMEM_A_HALF + srow * LDSY + sseg * 8) * 2;
        *reinterpret_cast<uint4*>(reinterpret_cast<char*>(sA) + hi_off) =
            *reinterpret_cast<const uint4*>(h);
        *reinterpret_cast<uint4*>(reinterpret_cast<char*>(sA) + lo_off) =
            *reinterpret_cast<const uint4*>(l);
    };

    int t0 = t_begin + blockIdx.x;
    if (t0 < t_end) {
        stage_load(t0, 0);
        CP_COMMIT();
        stage_store(0);
    } else {
        CP_COMMIT();
    }

    int buf = 0;
    for (int t = t0; t < t_end; t += GEMM_GRID) {
        int tn = t + GEMM_GRID;
        bool have_next = tn < t_end;
        if (have_next) stage_load(tn, buf ^ 1);
        CP_COMMIT();
        CP_WAIT1();
        __syncthreads();

        const __nv_bfloat16* bAh = sA + (buf * 2 + 0) * SMEM_A_HALF;
        const __nv_bfloat16* bAl = sA + (buf * 2 + 1) * SMEM_A_HALF;
        const __nv_bfloat16* aH0 = bAh + (band * 16 + g) * LDSY;
        const __nv_bfloat16* aL0 = bAl + (band * 16 + g) * LDSY;

        float c[2][4];
        #pragma unroll
        for (int n = 0; n < 2; n++)
            #pragma unroll
            for (int q = 0; q < 4; q++) c[n][q] = 0.0f;

        #pragma unroll
        for (int kt = 0; kt < 8; kt++) {
            int k = kt * 16;
            uint32_t ah[4], al[4];
            ah[0] = lds32(aH0 + k + tg * 2);
            ah[1] = lds32(aH0 + 8 * LDSY + k + tg * 2);
            ah[2] = lds32(aH0 + k + 8 + tg * 2);
            ah[3] = lds32(aH0 + 8 * LDSY + k + 8 + tg * 2);
            al[0] = lds32(aL0 + k + tg * 2);
            al[1] = lds32(aL0 + 8 * LDSY + k + tg * 2);
            al[2] = lds32(aL0 + k + 8 + tg * 2);
            al[3] = lds32(aL0 + 8 * LDSY + k + 8 + tg * 2);

            #pragma unroll
            for (int n = 0; n < 2; n++) {
                mma16816(c[n], ah, wfh[kt][n]);
                mma16816(c[n], al, wfh[kt][n]);
                mma16816(c[n], ah, wfl[kt][n]);
            }
        }

        int rowbase = t * TILE_M;
        int r0 = rowbase + band * 16 + g;
        int r1 = r0 + 8;
        #pragma unroll
        for (int n = 0; n < 2; n++) {
            int col = cg * 16 + n * 8 + tg * 2;
            if (r0 < N_NUM) {
                float2 o = make_float2(c[n][0] + bb[n].x, c[n][1] + bb[n].y);
                *reinterpret_cast<float2*>(out + (size_t)r0 * D_DIM + col) = o;
            }
            if (r1 < N_NUM) {
                float2 o = make_float2(c[n][2] + bb[n].x, c[n][3] + bb[n].y);
                *reinterpret_cast<float2*>(out + (size_t)r1 * D_DIM + col) = o;
            }
        }

        if (have_next) stage_store(buf ^ 1);
        buf ^= 1;
        __syncthreads();
    }
}

// ---------------- launch: 3-stream schedule ----------------
static cudaStream_t g_s2 = nullptr, g_s3 = nullptr;
static cudaEvent_t  g_evFork = nullptr, g_evJoin = nullptr, g_evId = nullptr;

extern "C" void kernel_launch(void* const* d_in, const int* in_sizes, int n_in,
                              void* d_out, int out_size) {
    const float* obj   = (const float*)d_in[0];
    const float* pred  = (const float*)d_in[1];
    const int*   e32   = (const int*)d_in[2];
    const float* W     = (const float*)d_in[3];
    const float* bias  = (const float*)d_in[4];
    float*       out   = (float*)d_out;

    if (g_s2 == nullptr) {
        cudaStreamCreateWithFlags(&g_s2, cudaStreamNonBlocking);
        cudaStreamCreateWithFlags(&g_s3, cudaStreamNonBlocking);
        cudaEventCreateWithFlags(&g_evFork, cudaEventDisableTiming);
        cudaEventCreateWithFlags(&g_evJoin, cudaEventDisableTiming);
        cudaEventCreateWithFlags(&g_evId, cudaEventDisableTiming);
        cudaFuncSetAttribute(gemm_fused_kernel,
                             cudaFuncAttributeMaxDynamicSharedMemorySize, GEMM_SMEM_BYTES);
    }

    // fork s3 from the capture-origin stream FIRST (graph-capture requires the
    // branch to be rooted in the origin), then run the dependency-free
    // identity-tile GEMM there, overlapping the serial prefix below.
    cudaEventRecord(g_evFork, 0);
    cudaStreamWaitEvent(g_s3, g_evFork, 0);
    gemm_fused_kernel<<<GEMM_GRID, 512, GEMM_SMEM_BYTES, g_s3>>>(
        obj, pred, e32, W, bias, out, TILE_ID_BEGIN, NT_TILES);
    cudaEventRecord(g_evId, g_s3);

    // serial prefix (stream 0)
    hist_all_kernel<<<HBLK + 1, 256>>>(e32);
    scan_block_kernel<<<NPART, 256>>>();
    scan_fix_kernel<<<NPART, 256>>>();

    // fork s2: scatter -> hard rows
    cudaEventRecord(g_evFork, 0);
    cudaStreamWaitEvent(g_s2, g_evFork, 0);
    csr_scatter_kernel<<<(T_NUM + 255) / 256, 256, 0, g_s2>>>(e32);
    agg_hard_kernel<<<(O_NUM + 7) / 8, 256, 0, g_s2>>>(obj, pred, e32);
    cudaEventRecord(g_evJoin, g_s2);

    // branch A (stream 0): easy-row GEMM (tiles [1563, 6250))
    gemm_fused_kernel<<<GEMM_GRID, 512, GEMM_SMEM_BYTES>>>(
        obj, pred, e32, W, bias, out, TILE_LOW_END, TILE_ID_BEGIN);

    // join both side streams, then low-tile GEMM (rows 0..50015)
    cudaStreamWaitEvent(0, g_evJoin, 0);
    cudaStreamWaitEvent(0, g_evId, 0);
    gemm_fused_kernel<<<GEMM_GRID, 512, GEMM_SMEM_BYTES>>>(
        obj, pred, e32, W, bias, out, 0, TILE_LOW_END);
}